// round 2
// baseline (speedup 1.0000x reference)
#include <cuda_runtime.h>
#include <cstdint>

#define BATCH 128
#define SEQ   512
#define IDIM  256
#define HDIM  512
#define G4    2048

// ---- persistent scan tiling ----
#define NBLK  128     // 4 batch-tiles x 32 j-tiles; all co-resident (<=148 SMs)
#define NTHR  128     // 4 warps
#define BJ    16      // j per block
#define BB    32      // batches per block
#define KC    128     // k chunk staged in smem
#define WROW  516     // padded weight row (floats): 2064B = 129*16B -> stride 1 line-slot mod 8
#define AROW  132     // padded h/c row: 528B = 33*16B
#define SMEM_SCAN ((64*WROW + 16*WROW + 2*BB*AROW)*4)

// ---- device-global scratch (no cudaMalloc allowed) ----
__device__ float g_h[2][BATCH][HDIM];
__device__ float g_c[2][BATCH][HDIM];
__device__ float g_u[SEQ][BATCH][G4];      // 512 MB precomputed input projection
__device__ unsigned g_bar[2];              // [0]=count, [1]=generation

// packed fp32x2 FMA (Blackwell-only; 2x FFMA throughput vs 3-reg FFMA)
__device__ __forceinline__ unsigned long long fma2(unsigned long long a,
                                                   unsigned long long b,
                                                   unsigned long long c) {
    unsigned long long d;
    asm("fma.rn.f32x2 %0, %1, %2, %3;" : "=l"(d) : "l"(a), "l"(b), "l"(c));
    return d;
}
__device__ __forceinline__ float red2(unsigned long long a) {
    return __uint_as_float((unsigned)a) + __uint_as_float((unsigned)(a >> 32));
}
__device__ __forceinline__ float sigm(float x) {
    return 1.0f / (1.0f + __expf(-x));
}

// =====================================================================
// Kernel 1: u_pre[s][b][g] = inputs[b][s][:] . U_all_w[g][:] + U_all_b[g]
// M=65536 (b*512+s), N=2048, K=256.  f32x2 k-packed SGEMM, 64x64x32 tiles.
// =====================================================================
__global__ void __launch_bounds__(256)
u_gemm_kernel(const float* __restrict__ X, const float* __restrict__ Uw,
              const float* __restrict__ Ub) {
    __shared__ float As[64][36];   // 144B row stride: 16B-aligned stores, 8B-aligned pair loads
    __shared__ float Bs[64][36];
    const int g0 = blockIdx.x * 64;
    const int r0 = blockIdx.y * 64;
    const int tid = threadIdx.x;
    const int tx = tid & 15, ty = tid >> 4;

    unsigned long long acc[4][4] = {};

    for (int k0 = 0; k0 < IDIM; k0 += 32) {
#pragma unroll
        for (int q = 0; q < 2; ++q) {
            int idx = tid + q * 256;
            int row = idx >> 3;
            int c4  = (idx & 7) << 2;
            *(float4*)&As[row][c4] = *(const float4*)&X[(size_t)(r0 + row) * IDIM + k0 + c4];
            *(float4*)&Bs[row][c4] = *(const float4*)&Uw[(size_t)(g0 + row) * IDIM + k0 + c4];
        }
        __syncthreads();
#pragma unroll
        for (int k = 0; k < 32; k += 2) {
            unsigned long long a[4], b[4];
#pragma unroll
            for (int i = 0; i < 4; ++i) a[i] = *(const unsigned long long*)&As[ty * 4 + i][k];
#pragma unroll
            for (int i = 0; i < 4; ++i) b[i] = *(const unsigned long long*)&Bs[tx * 4 + i][k];
#pragma unroll
            for (int mi = 0; mi < 4; ++mi)
#pragma unroll
                for (int ni = 0; ni < 4; ++ni)
                    acc[mi][ni] = fma2(a[mi], b[ni], acc[mi][ni]);
        }
        __syncthreads();
    }
#pragma unroll
    for (int mi = 0; mi < 4; ++mi) {
        int r = r0 + ty * 4 + mi;
        int b = r >> 9;          // batch
        int s = r & 511;         // step
        float* orow = &g_u[s][b][0];
#pragma unroll
        for (int ni = 0; ni < 4; ++ni) {
            int g = g0 + tx * 4 + ni;
            orow[g] = red2(acc[mi][ni]) + Ub[g];
        }
    }
}

// =====================================================================
// Kernel 2: persistent scan. 128 CTAs, weights resident in SMEM,
// grid barrier per step, h/c ping-pong through L2 (L1 bypassed via __ldcg).
// =====================================================================
__global__ void __launch_bounds__(NTHR, 1)
timelstm_scan_kernel(const float* __restrict__ Wall, const float* __restrict__ Wallb,
                     const float* __restrict__ Wd,   const float* __restrict__ Wdb,
                     const float* __restrict__ ts,   float* __restrict__ out) {
    extern __shared__ float sm[];
    float* sWg = sm;                         // 64 rows (4 gates x 16 j) x WROW
    float* sWd = sWg + 64 * WROW;            // 16 rows x WROW
    float* sh  = sWd + 16 * WROW;            // 32 x AROW
    float* sc  = sh  + BB * AROW;            // 32 x AROW

    const int tid = threadIdx.x;
    const int jt = blockIdx.x >> 2;          // 0..31
    const int bt = blockIdx.x & 3;           // 0..3
    const int j0 = jt * BJ;
    const int b0 = bt * BB;
    const int jj = tid >> 3;                 // 0..15  (4 j per warp -> LDS broadcast)
    const int bg = tid & 7;                  // 0..7
    const int j  = j0 + jj;
    const int bbase = b0 + bg * 4;

    // ---- preload weights into SMEM (once for all 512 steps) ----
    for (int idx = tid; idx < 64 * (HDIM / 4); idx += NTHR) {
        int row = idx >> 7;                  // HDIM/4 = 128 float4 per row
        int c4  = (idx & 127) << 2;
        int g = row >> 4, jl = row & 15;
        *(float4*)&sWg[row * WROW + c4] =
            *(const float4*)&Wall[(size_t)(g * HDIM + j0 + jl) * HDIM + c4];
    }
    for (int idx = tid; idx < 16 * (HDIM / 4); idx += NTHR) {
        int row = idx >> 7;
        int c4  = (idx & 127) << 2;
        *(float4*)&sWd[row * WROW + c4] =
            *(const float4*)&Wd[(size_t)(j0 + row) * HDIM + c4];
    }
    const float bf  = Wallb[0 * HDIM + j];
    const float bi_ = Wallb[1 * HDIM + j];
    const float bo  = Wallb[2 * HDIM + j];
    const float bct = Wallb[3 * HDIM + j];
    const float bd  = Wdb[j];
    __syncthreads();

    const float* wF = sWg + (0 * 16 + jj) * WROW;
    const float* wI = sWg + (1 * 16 + jj) * WROW;
    const float* wO = sWg + (2 * 16 + jj) * WROW;
    const float* wC = sWg + (3 * 16 + jj) * WROW;
    const float* wD = sWd + jj * WROW;

    for (int s = 0; s < SEQ; ++s) {
        const int cur = s & 1, nxt = cur ^ 1;

        // prefetch u, t, old c for the epilogue (long-latency, consumed late)
        float uf[4], ui[4], uo[4], uct[4], tv[4], cold[4];
#pragma unroll
        for (int q = 0; q < 4; ++q) {
            int b = bbase + q;
            const float* ub = &g_u[s][b][0];
            uf[q]  = ub[j];
            ui[q]  = ub[HDIM + j];
            uo[q]  = ub[2 * HDIM + j];
            uct[q] = ub[3 * HDIM + j];
            tv[q]  = ts[(size_t)b * SEQ + s];
            cold[q] = __ldcg(&g_c[cur][b][j]);
        }

        unsigned long long aF[4] = {}, aI[4] = {}, aO[4] = {}, aC[4] = {}, aD[4] = {};

        for (int kc = 0; kc < HDIM / KC; ++kc) {
            __syncthreads();   // previous chunk fully consumed
#pragma unroll
            for (int q = 0; q < (BB * KC / 4) / NTHR; ++q) {   // = 8
                int idx = tid + q * NTHR;
                int row = idx >> 5;
                int c4  = (idx & 31) << 2;
                int gk  = kc * KC + c4;
                *(float4*)&sh[row * AROW + c4] = __ldcg((const float4*)&g_h[cur][b0 + row][gk]);
                *(float4*)&sc[row * AROW + c4] = __ldcg((const float4*)&g_c[cur][b0 + row][gk]);
            }
            __syncthreads();

#pragma unroll 2
            for (int kk = 0; kk < KC; kk += 4) {
                const int k = kc * KC + kk;
                ulonglong2 vF = *(const ulonglong2*)(wF + k);
                ulonglong2 vI = *(const ulonglong2*)(wI + k);
                ulonglong2 vO = *(const ulonglong2*)(wO + k);
                ulonglong2 vC = *(const ulonglong2*)(wC + k);
                ulonglong2 vD = *(const ulonglong2*)(wD + k);
#pragma unroll
                for (int q = 0; q < 4; ++q) {
                    const float* hr = sh + (bg * 4 + q) * AROW + kk;
                    const float* cr = sc + (bg * 4 + q) * AROW + kk;
                    ulonglong2 hv = *(const ulonglong2*)hr;
                    ulonglong2 cv = *(const ulonglong2*)cr;
                    aF[q] = fma2(hv.x, vF.x, aF[q]); aF[q] = fma2(hv.y, vF.y, aF[q]);
                    aI[q] = fma2(hv.x, vI.x, aI[q]); aI[q] = fma2(hv.y, vI.y, aI[q]);
                    aO[q] = fma2(hv.x, vO.x, aO[q]); aO[q] = fma2(hv.y, vO.y, aO[q]);
                    aC[q] = fma2(hv.x, vC.x, aC[q]); aC[q] = fma2(hv.y, vC.y, aC[q]);
                    aD[q] = fma2(cv.x, vD.x, aD[q]); aD[q] = fma2(cv.y, vD.y, aD[q]);
                }
            }
        }

        // ---- epilogue: gates + time-decay cell update ----
#pragma unroll
        for (int q = 0; q < 4; ++q) {
            int b = bbase + q;
            float F  = red2(aF[q]) + bf  + uf[q];
            float I_ = red2(aI[q]) + bi_ + ui[q];
            float O_ = red2(aO[q]) + bo  + uo[q];
            float Ct = red2(aC[q]) + bct + uct[q];
            float D  = red2(aD[q]) + bd;
            float f  = sigm(F);
            float ii = sigm(I_);
            float oo = sigm(O_);
            float ct = sigm(Ct);
            float cs1 = tanhf(D);
            float cadj = cold[q] + cs1 * (tv[q] - 1.0f);   // c - cs1 + cs1*t
            float cnew = f * cadj + ii * ct;
            float hnew = oo * tanhf(cnew);
            g_c[nxt][b][j] = cnew;
            g_h[nxt][b][j] = hnew;
            out[((size_t)b * SEQ + s) * HDIM + j] = hnew;
        }

        // ---- grid barrier (sense via generation counter) ----
        __syncthreads();
        if (tid == 0) {
            volatile unsigned* vgen = &g_bar[1];
            unsigned gen = *vgen;
            __threadfence();
            if (atomicAdd(&g_bar[0], 1u) == NBLK - 1u) {
                g_bar[0] = 0u;
                __threadfence();
                *vgen = gen + 1u;
            } else {
                while (*vgen == gen) { }
            }
            __threadfence();
        }
        __syncthreads();
    }
}

// =====================================================================
extern "C" void kernel_launch(void* const* d_in, const int* in_sizes, int n_in,
                              void* d_out, int out_size) {
    const float* X     = (const float*)d_in[0];   // inputs   [B,S,I]
    const float* T     = (const float*)d_in[1];   // timestamps [B,S]
    const float* Wall  = (const float*)d_in[2];   // W_all_w  [4H,H]
    const float* Wallb = (const float*)d_in[3];   // W_all_b  [4H]
    const float* Uw    = (const float*)d_in[4];   // U_all_w  [4H,I]
    const float* Ubb   = (const float*)d_in[5];   // U_all_b  [4H]
    const float* Wd    = (const float*)d_in[6];   // W_d_w    [H,H]
    const float* Wdb   = (const float*)d_in[7];   // W_d_b    [H]
    float* out = (float*)d_out;

    void *hp, *cp, *bp;
    cudaGetSymbolAddress(&hp, g_h);
    cudaGetSymbolAddress(&cp, g_c);
    cudaGetSymbolAddress(&bp, g_bar);
    cudaMemsetAsync(hp, 0, sizeof(float) * 2 * BATCH * HDIM, 0);
    cudaMemsetAsync(cp, 0, sizeof(float) * 2 * BATCH * HDIM, 0);
    cudaMemsetAsync(bp, 0, sizeof(unsigned) * 2, 0);

    dim3 ugrid(G4 / 64, (BATCH * SEQ) / 64);
    u_gemm_kernel<<<ugrid, 256>>>(X, Uw, Ubb);

    cudaFuncSetAttribute(timelstm_scan_kernel,
                         cudaFuncAttributeMaxDynamicSharedMemorySize, SMEM_SCAN);
    timelstm_scan_kernel<<<NBLK, NTHR, SMEM_SCAN>>>(Wall, Wallb, Wd, Wdb, T, out);
}

// round 3
// speedup vs baseline: 1.5689x; 1.5689x over previous
#include <cuda_runtime.h>
#include <cstdint>

#define BATCH 128
#define SEQ   512
#define IDIM  256
#define HDIM  512
#define G4    2048

// ---- persistent scan tiling ----
#define NBLK  128     // 4 batch-tiles x 32 j-tiles; all co-resident (<=148 SMs)
#define NTHR  512     // 16 warps -> 4 warps per SMSP (latency hiding)
#define BJ    16      // j per block
#define BB    32      // batches per block
#define KC    128     // k chunk staged in smem
#define WROW  516     // padded weight row (floats): rows offset by 4 banks
#define AROW  132     // padded h/c row: rows offset by 4 banks
#define SMEM_SCAN ((64*WROW + 16*WROW + 2*BB*AROW)*4)

// ---- device-global scratch (no cudaMalloc allowed) ----
__device__ float g_h[2][BATCH][HDIM];
__device__ float g_c[2][BATCH][HDIM];
__device__ float g_u[SEQ][BATCH][G4];      // 512 MB precomputed input projection
__device__ unsigned g_bar[2];              // [0]=count, [1]=generation

// packed fp32x2 FMA (Blackwell-only; 2x FFMA throughput vs 3-reg FFMA)
__device__ __forceinline__ unsigned long long fma2(unsigned long long a,
                                                   unsigned long long b,
                                                   unsigned long long c) {
    unsigned long long d;
    asm("fma.rn.f32x2 %0, %1, %2, %3;" : "=l"(d) : "l"(a), "l"(b), "l"(c));
    return d;
}
__device__ __forceinline__ float red2(unsigned long long a) {
    return __uint_as_float((unsigned)a) + __uint_as_float((unsigned)(a >> 32));
}
__device__ __forceinline__ float sigm(float x) {
    return 1.0f / (1.0f + __expf(-x));
}

// =====================================================================
// Kernel 1: u_pre[s][b][g] = inputs[b][s][:] . U_all_w[g][:] + U_all_b[g]
// M=65536 (b*512+s), N=2048, K=256.  f32x2 k-packed SGEMM, 64x64x32 tiles.
// =====================================================================
__global__ void __launch_bounds__(256)
u_gemm_kernel(const float* __restrict__ X, const float* __restrict__ Uw,
              const float* __restrict__ Ub) {
    __shared__ float As[64][36];
    __shared__ float Bs[64][36];
    const int g0 = blockIdx.x * 64;
    const int r0 = blockIdx.y * 64;
    const int tid = threadIdx.x;
    const int tx = tid & 15, ty = tid >> 4;

    unsigned long long acc[4][4] = {};

    for (int k0 = 0; k0 < IDIM; k0 += 32) {
#pragma unroll
        for (int q = 0; q < 2; ++q) {
            int idx = tid + q * 256;
            int row = idx >> 3;
            int c4  = (idx & 7) << 2;
            *(float4*)&As[row][c4] = *(const float4*)&X[(size_t)(r0 + row) * IDIM + k0 + c4];
            *(float4*)&Bs[row][c4] = *(const float4*)&Uw[(size_t)(g0 + row) * IDIM + k0 + c4];
        }
        __syncthreads();
#pragma unroll
        for (int k = 0; k < 32; k += 2) {
            unsigned long long a[4], b[4];
#pragma unroll
            for (int i = 0; i < 4; ++i) a[i] = *(const unsigned long long*)&As[ty * 4 + i][k];
#pragma unroll
            for (int i = 0; i < 4; ++i) b[i] = *(const unsigned long long*)&Bs[tx * 4 + i][k];
#pragma unroll
            for (int mi = 0; mi < 4; ++mi)
#pragma unroll
                for (int ni = 0; ni < 4; ++ni)
                    acc[mi][ni] = fma2(a[mi], b[ni], acc[mi][ni]);
        }
        __syncthreads();
    }
#pragma unroll
    for (int mi = 0; mi < 4; ++mi) {
        int r = r0 + ty * 4 + mi;
        int b = r >> 9;          // batch
        int s = r & 511;         // step
        float* orow = &g_u[s][b][0];
#pragma unroll
        for (int ni = 0; ni < 4; ++ni) {
            int g = g0 + tx * 4 + ni;
            orow[g] = red2(acc[mi][ni]) + Ub[g];
        }
    }
}

// =====================================================================
// Kernel 2: persistent scan. 128 CTAs x 512 threads (4 warps/SMSP).
// Weights resident in SMEM for all 512 steps; h/c ping-pong via L2.
// Per thread: 1 batch x 1 j, 5 accumulators (F,I,O,Ctmp,Decay).
// Warp layout: 8 batches x 4 j -> weight LDS 8-way broadcast,
// h/c LDS 4-way broadcast, all conflict-free.
// =====================================================================
__global__ void __launch_bounds__(NTHR, 1)
timelstm_scan_kernel(const float* __restrict__ Wall, const float* __restrict__ Wallb,
                     const float* __restrict__ Wd,   const float* __restrict__ Wdb,
                     const float* __restrict__ ts,   float* __restrict__ out) {
    extern __shared__ float sm[];
    float* sWg = sm;                         // 64 rows (4 gates x 16 j) x WROW
    float* sWd = sWg + 64 * WROW;            // 16 rows x WROW
    float* sh  = sWd + 16 * WROW;            // 32 x AROW
    float* sc  = sh  + BB * AROW;            // 32 x AROW

    const int tid  = threadIdx.x;
    const int warp = tid >> 5;
    const int lane = tid & 31;
    const int jt = blockIdx.x >> 2;          // 0..31
    const int bt = blockIdx.x & 3;           // 0..3
    const int j0 = jt * BJ;
    const int b0 = bt * BB;

    const int bl = (warp & 3) * 8 + (lane & 7);   // local batch 0..31
    const int jj = (warp >> 2) * 4 + (lane >> 3); // local j     0..15
    const int b  = b0 + bl;
    const int j  = j0 + jj;

    // ---- preload weights into SMEM (once for all 512 steps) ----
    for (int idx = tid; idx < 64 * (HDIM / 4); idx += NTHR) {
        int row = idx >> 7;                  // HDIM/4 = 128 float4 per row
        int c4  = (idx & 127) << 2;
        int g = row >> 4, jl = row & 15;
        *(float4*)&sWg[row * WROW + c4] =
            *(const float4*)&Wall[(size_t)(g * HDIM + j0 + jl) * HDIM + c4];
    }
    for (int idx = tid; idx < 16 * (HDIM / 4); idx += NTHR) {
        int row = idx >> 7;
        int c4  = (idx & 127) << 2;
        *(float4*)&sWd[row * WROW + c4] =
            *(const float4*)&Wd[(size_t)(j0 + row) * HDIM + c4];
    }
    const float bf  = Wallb[0 * HDIM + j];
    const float bi_ = Wallb[1 * HDIM + j];
    const float bo  = Wallb[2 * HDIM + j];
    const float bct = Wallb[3 * HDIM + j];
    const float bd  = Wdb[j];
    __syncthreads();

    const float* wF = sWg + (0 * 16 + jj) * WROW;
    const float* wI = sWg + (1 * 16 + jj) * WROW;
    const float* wO = sWg + (2 * 16 + jj) * WROW;
    const float* wC = sWg + (3 * 16 + jj) * WROW;
    const float* wD = sWd + jj * WROW;
    const float* hrow = sh + bl * AROW;
    const float* crow = sc + bl * AROW;

    for (int s = 0; s < SEQ; ++s) {
        const int cur = s & 1, nxt = cur ^ 1;

        // prefetch u, t, old c for the epilogue (long-latency, consumed late)
        const float* ub = &g_u[s][b][0];
        float uf   = ub[j];
        float ui   = ub[HDIM + j];
        float uo   = ub[2 * HDIM + j];
        float uct  = ub[3 * HDIM + j];
        float tv   = ts[(size_t)b * SEQ + s];
        float cold = __ldcg(&g_c[cur][b][j]);

        unsigned long long aF = 0, aI = 0, aO = 0, aC = 0, aD = 0;

        for (int kc = 0; kc < HDIM / KC; ++kc) {
            __syncthreads();   // previous chunk fully consumed
#pragma unroll
            for (int q = 0; q < (BB * KC / 4) / NTHR; ++q) {   // = 2
                int idx = tid + q * NTHR;
                int row = idx >> 5;
                int c4  = (idx & 31) << 2;
                int gk  = kc * KC + c4;
                *(float4*)&sh[row * AROW + c4] = __ldcg((const float4*)&g_h[cur][b0 + row][gk]);
                *(float4*)&sc[row * AROW + c4] = __ldcg((const float4*)&g_c[cur][b0 + row][gk]);
            }
            __syncthreads();

#pragma unroll 8
            for (int kk = 0; kk < KC; kk += 4) {
                const int k = kc * KC + kk;
                ulonglong2 vF = *(const ulonglong2*)(wF + k);
                ulonglong2 vI = *(const ulonglong2*)(wI + k);
                ulonglong2 vO = *(const ulonglong2*)(wO + k);
                ulonglong2 vC = *(const ulonglong2*)(wC + k);
                ulonglong2 vD = *(const ulonglong2*)(wD + k);
                ulonglong2 hv = *(const ulonglong2*)(hrow + kk);
                ulonglong2 cv = *(const ulonglong2*)(crow + kk);
                aF = fma2(hv.x, vF.x, aF);
                aI = fma2(hv.x, vI.x, aI);
                aO = fma2(hv.x, vO.x, aO);
                aC = fma2(hv.x, vC.x, aC);
                aD = fma2(cv.x, vD.x, aD);
                aF = fma2(hv.y, vF.y, aF);
                aI = fma2(hv.y, vI.y, aI);
                aO = fma2(hv.y, vO.y, aO);
                aC = fma2(hv.y, vC.y, aC);
                aD = fma2(cv.y, vD.y, aD);
            }
        }

        // ---- epilogue: gates + time-decay cell update ----
        {
            float F  = red2(aF) + bf  + uf;
            float I_ = red2(aI) + bi_ + ui;
            float O_ = red2(aO) + bo  + uo;
            float Ct = red2(aC) + bct + uct;
            float D  = red2(aD) + bd;
            float f  = sigm(F);
            float ii = sigm(I_);
            float oo = sigm(O_);
            float ct = sigm(Ct);
            float cs1 = tanhf(D);
            float cadj = cold + cs1 * (tv - 1.0f);   // c - cs1 + cs1*t
            float cnew = f * cadj + ii * ct;
            float hnew = oo * tanhf(cnew);
            g_c[nxt][b][j] = cnew;
            g_h[nxt][b][j] = hnew;
            out[((size_t)b * SEQ + s) * HDIM + j] = hnew;
        }

        // ---- grid barrier (sense via generation counter) ----
        __syncthreads();
        if (tid == 0) {
            volatile unsigned* vgen = &g_bar[1];
            unsigned gen = *vgen;
            __threadfence();
            if (atomicAdd(&g_bar[0], 1u) == NBLK - 1u) {
                g_bar[0] = 0u;
                __threadfence();
                *vgen = gen + 1u;
            } else {
                while (*vgen == gen) { }
            }
            __threadfence();
        }
        __syncthreads();
    }
}

// =====================================================================
extern "C" void kernel_launch(void* const* d_in, const int* in_sizes, int n_in,
                              void* d_out, int out_size) {
    const float* X     = (const float*)d_in[0];   // inputs   [B,S,I]
    const float* T     = (const float*)d_in[1];   // timestamps [B,S]
    const float* Wall  = (const float*)d_in[2];   // W_all_w  [4H,H]
    const float* Wallb = (const float*)d_in[3];   // W_all_b  [4H]
    const float* Uw    = (const float*)d_in[4];   // U_all_w  [4H,I]
    const float* Ubb   = (const float*)d_in[5];   // U_all_b  [4H]
    const float* Wd    = (const float*)d_in[6];   // W_d_w    [H,H]
    const float* Wdb   = (const float*)d_in[7];   // W_d_b    [H]
    float* out = (float*)d_out;

    void *hp, *cp, *bp;
    cudaGetSymbolAddress(&hp, g_h);
    cudaGetSymbolAddress(&cp, g_c);
    cudaGetSymbolAddress(&bp, g_bar);
    cudaMemsetAsync(hp, 0, sizeof(float) * 2 * BATCH * HDIM, 0);
    cudaMemsetAsync(cp, 0, sizeof(float) * 2 * BATCH * HDIM, 0);
    cudaMemsetAsync(bp, 0, sizeof(unsigned) * 2, 0);

    dim3 ugrid(G4 / 64, (BATCH * SEQ) / 64);
    u_gemm_kernel<<<ugrid, 256>>>(X, Uw, Ubb);

    cudaFuncSetAttribute(timelstm_scan_kernel,
                         cudaFuncAttributeMaxDynamicSharedMemorySize, SMEM_SCAN);
    timelstm_scan_kernel<<<NBLK, NTHR, SMEM_SCAN>>>(Wall, Wallb, Wd, Wdb, T, out);
}